// round 17
// baseline (speedup 1.0000x reference)
#include <cuda_runtime.h>
#include <cuda_fp16.h>

#define N_NODES 100000
#define N_EDGES 1600000
#define HMW 32            // concatenated mu(16) | logstd(16)
#define OUTC 16

// ---------------- scratch (device globals; zero at module load) ------------------
// deg/acc0 are accumulators: zeroed at tail of k_scatter1 for the NEXT launch
// (module-load zero covers launch 1). gvech/acc1h/dis are fully overwritten by
// k_hidden each launch (acc1h's overwrite IS its initialization: fp16 self term).
__device__ float  g_deg  [N_NODES];         // in-degree count (dst)
__device__ float  g_acc0 [N_NODES * 2];     // layer-1 aggregation of dis*x
__device__ float  g_dis  [N_NODES];         // rsqrt(1+deg), written by k_hidden
__device__ __half g_gvech[N_NODES * HMW];   // gvec fp16 (gather payload + REDG operand)
__device__ __half g_acc1h[N_NODES * HMW];   // fp16 accumulator, seeded = fp16 self term

// ---------------- PDL primitives (sm_90+) ----------------------------------------
// launch_dependents: allow the NEXT kernel in the stream to launch early.
// wait: block until the PREVIOUS kernel has fully completed (memory visible).
// If a launch lacks the PSS attribute (fallback path), wait is a no-op.
__device__ __forceinline__ void pdl_launch() {
    asm volatile("griddepcontrol.launch_dependents;");
}
__device__ __forceinline__ void pdl_wait() {
    asm volatile("griddepcontrol.wait;");
}

// ---------------- vectorized L2 reductions (sm_90+) -----------------------------
__device__ __forceinline__ void red_add_v2(float* addr, float a, float b) {
    asm volatile("red.global.add.v2.f32 [%0], {%1, %2};"
                 :: "l"(addr), "f"(a), "f"(b) : "memory");
}
// 8 packed halves (4 x f16x2) in one 16B reduction lane
__device__ __forceinline__ void red_add_v4h2(__half* addr, uint4 w) {
    asm volatile("red.global.add.noftz.v4.f16x2 [%0], {%1, %2, %3, %4};"
                 :: "l"(addr), "r"(w.x), "r"(w.y), "r"(w.z), "r"(w.w) : "memory");
}

// ---------------- local dtype detect (input-only; safe pre-wait) -----------------
// 256 odd words sampled per block. int64 indices < 100000 have zero high words;
// int32 data puts edge values there (P(all 256 == 0) astronomically small).
__device__ __forceinline__ int detect_is64(const void* ei, unsigned* s_or) {
    int t = threadIdx.x;
    s_or[t] = ((const unsigned*)ei)[2 * t + 1];
    __syncthreads();
    for (int s = 128; s > 0; s >>= 1) {
        if (t < s) s_or[t] |= s_or[t + s];
        __syncthreads();
    }
    return (s_or[0] == 0u) ? 1 : 0;
}

__device__ __forceinline__ void load_edge_raw(const void* ei, int is64, int e,
                                              int& src, int& dst) {
    if (is64) {
        const long long* p = (const long long*)ei;
        src = (int)p[e];
        dst = (int)p[N_EDGES + e];
    } else {
        const int* p = (const int*)ei;
        src = p[e];
        dst = p[N_EDGES + e];
    }
}

// ---------------- degree -----------------------------------------------------------
// Pre-wait: dtype detect + dst load (inputs only). Post-wait (prev replay's k_out
// complete => scatter1's deg/acc0 zeroing complete): atomics.
__global__ void k_deg(const void* ei) {
    pdl_launch();                       // scatter0's pre-wait work is input-only
    __shared__ unsigned s_or[256];
    int is64 = detect_is64(ei, s_or);
    int e = blockIdx.x * 256 + threadIdx.x;
    int dst = 0;
    bool valid = (e < N_EDGES);
    if (valid) {
        if (is64) dst = (int)((const long long*)ei)[N_EDGES + e];
        else      dst = ((const int*)ei)[N_EDGES + e];
    }
    pdl_wait();
    if (valid) atomicAdd(&g_deg[dst], 1.0f);
}

// ---------------- layer-1 scatter: acc0[dst] += dis[src] * x[src]  (2 feats) ----
// Pre-wait: detect + edge idx + x[src] (inputs). Post-wait (deg complete): REDG.
__global__ void k_scatter0(const void* ei, const float* __restrict__ x) {
    pdl_launch();                       // k_hidden's pre-wait work is input-only
    __shared__ unsigned s_or[256];
    int is64 = detect_is64(ei, s_or);
    int e = blockIdx.x * 256 + threadIdx.x;
    int src = 0, dst = 0;
    float2 xv = make_float2(0.f, 0.f);
    bool valid = (e < N_EDGES);
    if (valid) {
        load_edge_raw(ei, is64, e, src, dst);
        xv = ((const float2*)x)[src];
    }
    pdl_wait();
    if (valid) {
        float ds = rsqrtf(1.0f + g_deg[src]);
        red_add_v2(&g_acc0[2 * dst], ds * xv.x, ds * xv.y);
    }
}

// ---------------- dense: h = relu(aggX @ W1 + b1); g = dis * (h @ [Wmu|Wls]) ----
// 4 threads/node (8 outputs each) x 4 nodes/thread (R6/R8-proven shape).
// Pre-wait: stage weights to smem + load x (inputs). Post-wait: deg/acc0 reads,
// compute, write gvech (payload) + acc1h (fp16 self seed) + dis.
__global__ void __launch_bounds__(256) k_hidden(
        const float* __restrict__ x, const float* __restrict__ W1,
        const float* __restrict__ b1,
        const float* __restrict__ Wmu, const float* __restrict__ Wls) {
    __shared__ float4 sW4[64][8];   // [k][j/4] of concatenated [Wmu|Wls]
    __shared__ float4 sWb[64];      // (W1[0][k], W1[1][k], b1[k], 0)

    pdl_launch();                       // scatter1's pre-wait work is input-only
    int t = threadIdx.x;
    for (int i = t; i < 512; i += 256) {
        int k = i >> 3, q = i & 7;
        sW4[k][q] = (q < 4) ? ((const float4*)Wmu)[k * 4 + q]
                            : ((const float4*)Wls)[k * 4 + (q - 4)];
    }
    if (t < 64) sWb[t] = make_float4(W1[t], W1[64 + t], b1[t], 0.0f);

    int part = t & 3;               // which 8 of the 32 outputs
    int u    = t >> 2;              // 0..63
    int base = blockIdx.x * 256;

    float2 xv[4];
    #pragma unroll
    for (int i = 0; i < 4; i++) {
        int n = base + u + 64 * i;
        xv[i] = ((const float2*)x)[(n < N_NODES) ? n : 0];
    }
    __syncthreads();                    // weights staged
    pdl_wait();                         // deg + acc0 ready

    float a0[4], a1[4], dd[4];
    #pragma unroll
    for (int i = 0; i < 4; i++) {
        int n = base + u + 64 * i;
        int nc = (n < N_NODES) ? n : 0;
        float d = rsqrtf(1.0f + g_deg[nc]);
        float2 av = ((const float2*)g_acc0)[nc];
        a0[i] = d * av.x + d * d * xv[i].x;
        a1[i] = d * av.y + d * d * xv[i].y;
        dd[i] = d;
    }

    float acc[4][8];
    #pragma unroll
    for (int i = 0; i < 4; i++)
        #pragma unroll
        for (int j = 0; j < 8; j++) acc[i][j] = 0.0f;

    int q0 = part * 2;
    #pragma unroll 4
    for (int k = 0; k < 64; k++) {
        float4 wb = sWb[k];
        float4 wA = sW4[k][q0];
        float4 wB = sW4[k][q0 + 1];
        #pragma unroll
        for (int i = 0; i < 4; i++) {
            float hk = fmaxf(0.0f, fmaf(a0[i], wb.x, fmaf(a1[i], wb.y, wb.z)));
            acc[i][0] = fmaf(hk, wA.x, acc[i][0]);
            acc[i][1] = fmaf(hk, wA.y, acc[i][1]);
            acc[i][2] = fmaf(hk, wA.z, acc[i][2]);
            acc[i][3] = fmaf(hk, wA.w, acc[i][3]);
            acc[i][4] = fmaf(hk, wB.x, acc[i][4]);
            acc[i][5] = fmaf(hk, wB.y, acc[i][5]);
            acc[i][6] = fmaf(hk, wB.z, acc[i][6]);
            acc[i][7] = fmaf(hk, wB.w, acc[i][7]);
        }
    }

    #pragma unroll
    for (int i = 0; i < 4; i++) {
        int n = base + u + 64 * i;
        if (n < N_NODES) {
            __half2 h0 = __float22half2_rn(make_float2(dd[i] * acc[i][0], dd[i] * acc[i][1]));
            __half2 h1 = __float22half2_rn(make_float2(dd[i] * acc[i][2], dd[i] * acc[i][3]));
            __half2 h2 = __float22half2_rn(make_float2(dd[i] * acc[i][4], dd[i] * acc[i][5]));
            __half2 h3 = __float22half2_rn(make_float2(dd[i] * acc[i][6], dd[i] * acc[i][7]));
            uint4 pk;
            pk.x = *(unsigned*)&h0; pk.y = *(unsigned*)&h1;
            pk.z = *(unsigned*)&h2; pk.w = *(unsigned*)&h3;
            *(uint4*)(g_gvech + n * HMW + part * 8) = pk;   // scatter payload
            *(uint4*)(g_acc1h + n * HMW + part * 8) = pk;   // accumulator seed
            if (part == 0) g_dis[n] = dd[i];                // persist for epilogue
        }
    }
}

// ---------------- layer-2 scatter (fp16 packed REDG) + accumulator re-zeroing ----
// Pre-wait: detect + edge idx (inputs, read straight from ei — no compaction).
// Post-wait (hidden complete): 4 threads/edge, each gathers one uint4 of
// gvech[src] and fires ONE red.v4.f16x2 -> 6.4M REDG lanes. Tail range zeroes
// deg + acc0 for the NEXT launch (safe: hidden was their last reader).
#define S1_EDGE_T (N_EDGES * 4)
#define S1_ZD     (N_NODES / 4)          // deg float4s   (25000)
#define S1_ZA     (N_NODES * 2 / 4)      // acc0 float4s  (50000)
#define S1_TOTAL  (S1_EDGE_T + S1_ZD + S1_ZA)
__global__ void k_scatter1(const void* ei) {
    pdl_launch();                       // k_out's pre-wait work is input-only
    __shared__ unsigned s_or[256];
    int is64 = detect_is64(ei, s_or);
    int tid = blockIdx.x * 256 + threadIdx.x;
    int src = 0, dst = 0, q = 0;
    bool edge = (tid < S1_EDGE_T);
    if (edge) {
        int e = tid >> 2;
        q = tid & 3;
        load_edge_raw(ei, is64, e, src, dst);
    }
    pdl_wait();
    if (edge) {
        uint4 w = ((const uint4*)g_gvech)[src * 4 + q];     // 8 halves
        red_add_v4h2(g_acc1h + dst * HMW + q * 8, w);
    } else {
        int z = tid - S1_EDGE_T;
        const float4 zero = make_float4(0.f, 0.f, 0.f, 0.f);
        if (z < S1_ZD)                ((float4*)g_deg )[z] = zero;
        else if (z < S1_ZD + S1_ZA)   ((float4*)g_acc0)[z - S1_ZD] = zero;
    }
}

// ---------------- epilogue: out = dis*acc1h + bias; split mu / logstd -----------
// launch_dependents at entry lets the NEXT REPLAY's k_deg start its input-only
// prologue early; k_deg's atomics wait for k_out completion (=> zeroing done).
__global__ void k_out(const float* __restrict__ bmu, const float* __restrict__ bls,
                      float* __restrict__ out) {
    pdl_launch();
    int tid = blockIdx.x * 256 + threadIdx.x;       // over N_NODES * 8 quads
    float4 b = make_float4(0.f, 0.f, 0.f, 0.f);
    int n = tid >> 3, q = tid & 7;
    bool valid = (tid < N_NODES * 8);
    if (valid) b = (q < 4) ? ((const float4*)bmu)[q] : ((const float4*)bls)[q - 4];
    pdl_wait();
    if (!valid) return;
    float d = g_dis[n];
    uint2 hw = ((const uint2*)g_acc1h)[tid];        // 4 halves (self + neighbors)
    float2 f0 = __half22float2(*(__half2*)&hw.x);
    float2 f1 = __half22float2(*(__half2*)&hw.y);
    float4 v = make_float4(fmaf(d, f0.x, b.x), fmaf(d, f0.y, b.y),
                           fmaf(d, f1.x, b.z), fmaf(d, f1.y, b.w));
    float* dst = (q < 4) ? out + n * OUTC + q * 4
                         : out + N_NODES * OUTC + n * OUTC + (q - 4) * 4;
    *(float4*)dst = v;
}

// ---------------- host: PDL launches with plain fallback -------------------------
static void launch_pdl(const void* func, int grid, int block, void** args) {
    cudaLaunchConfig_t cfg = {};
    cfg.gridDim = dim3(grid, 1, 1);
    cfg.blockDim = dim3(block, 1, 1);
    cfg.dynamicSmemBytes = 0;
    cfg.stream = 0;                              // legacy default (capture target)
    cudaLaunchAttribute attr[1];
    attr[0].id = cudaLaunchAttributeProgrammaticStreamSerialization;
    attr[0].val.programmaticStreamSerializationAllowed = 1;
    cfg.attrs = attr;
    cfg.numAttrs = 1;
    if (cudaLaunchKernelExC(&cfg, func, args) != cudaSuccess) {
        // PSS unsupported: plain launch; griddepcontrol.wait degrades to no-op
        cudaLaunchKernel(func, dim3(grid, 1, 1), dim3(block, 1, 1), args, 0, 0);
    }
}

extern "C" void kernel_launch(void* const* d_in, const int* in_sizes, int n_in,
                              void* d_out, int out_size) {
    const float* x    = (const float*)d_in[0];
    const void*  ei   = d_in[1];                 // int32 or int64, detected on device
    const float* W1   = (const float*)d_in[2];
    const float* b1   = (const float*)d_in[3];
    const float* Wmu  = (const float*)d_in[4];
    const float* bmu  = (const float*)d_in[5];
    const float* Wls  = (const float*)d_in[6];
    const float* bls  = (const float*)d_in[7];
    float* out = (float*)d_out;

    const int EB  = (N_EDGES + 255) / 256;                // 6250
    const int HB  = (N_NODES + 255) / 256;                // 391
    const int OB  = (N_NODES * 8 + 255) / 256;            // 3125
    const int S1B = (S1_TOTAL + 255) / 256;               // 25293

    void* a_deg[] = { (void*)&ei };
    launch_pdl((const void*)k_deg, EB, 256, a_deg);

    void* a_s0[] = { (void*)&ei, (void*)&x };
    launch_pdl((const void*)k_scatter0, EB, 256, a_s0);

    void* a_hid[] = { (void*)&x, (void*)&W1, (void*)&b1, (void*)&Wmu, (void*)&Wls };
    launch_pdl((const void*)k_hidden, HB, 256, a_hid);

    void* a_s1[] = { (void*)&ei };
    launch_pdl((const void*)k_scatter1, S1B, 256, a_s1);

    void* a_out[] = { (void*)&bmu, (void*)&bls, (void*)&out };
    launch_pdl((const void*)k_out, OB, 256, a_out);
}